// round 3
// baseline (speedup 1.0000x reference)
#include <cuda_runtime.h>
#include <math.h>

#define D_MODEL 1024
#define S_LEN   2048
#define BATCH   2
#define N_HEADS 16
#define HD      64
#define M_ROWS  (BATCH * S_LEN)   // 4096

// Scratch (no cudaMalloc allowed): Q, K, V projections + attention output.
__device__ float g_Q[M_ROWS * D_MODEL];
__device__ float g_K[M_ROWS * D_MODEL];
__device__ float g_V[M_ROWS * D_MODEL];
__device__ float g_AO[M_ROWS * D_MODEL];

// ---------------------------------------------------------------------------
// NT GEMM: C[M,N] = A[M,K] * B[N,K]^T (+ bias), both A and B row-major with K
// contiguous (nn.Linear x @ W.T layout). 128x128 tile, BK=8, 256 threads,
// 8x8 per thread in split-quad (4+4) mapping to limit smem bank conflicts.
// ---------------------------------------------------------------------------
__global__ __launch_bounds__(256) void gemm_nt_kernel(
    const float* __restrict__ A, const float* __restrict__ B,
    const float* __restrict__ bias, float* __restrict__ C,
    int M, int N, int K)
{
    __shared__ float As[8][128];
    __shared__ float Bs[8][128];

    const int tid = threadIdx.x;
    const int ty  = tid >> 4;       // 0..15
    const int tx  = tid & 15;       // 0..15
    const int row0 = blockIdx.y * 128;
    const int col0 = blockIdx.x * 128;

    const int lr  = tid >> 1;       // 0..127: load row within tile
    const int lc  = (tid & 1) * 4;  // 0 or 4: float4 column within BK=8

    const float* Ap = A + (size_t)(row0 + lr) * K + lc;
    const float* Bp = B + (size_t)(col0 + lr) * K + lc;

    float acc[8][8];
#pragma unroll
    for (int i = 0; i < 8; i++)
#pragma unroll
        for (int j = 0; j < 8; j++) acc[i][j] = 0.0f;

    for (int k0 = 0; k0 < K; k0 += 8) {
        float4 av = *(const float4*)(Ap + k0);
        float4 bv = *(const float4*)(Bp + k0);
        __syncthreads();  // previous iteration's compute must finish
        As[lc + 0][lr] = av.x; As[lc + 1][lr] = av.y;
        As[lc + 2][lr] = av.z; As[lc + 3][lr] = av.w;
        Bs[lc + 0][lr] = bv.x; Bs[lc + 1][lr] = bv.y;
        Bs[lc + 2][lr] = bv.z; Bs[lc + 3][lr] = bv.w;
        __syncthreads();

#pragma unroll
        for (int k = 0; k < 8; k++) {
            float a[8], b[8];
#pragma unroll
            for (int i = 0; i < 4; i++) {
                a[i]     = As[k][ty * 4 + i];
                a[i + 4] = As[k][64 + ty * 4 + i];
                b[i]     = Bs[k][tx * 4 + i];
                b[i + 4] = Bs[k][64 + tx * 4 + i];
            }
#pragma unroll
            for (int i = 0; i < 8; i++)
#pragma unroll
                for (int j = 0; j < 8; j++)
                    acc[i][j] = fmaf(a[i], b[j], acc[i][j]);
        }
    }

#pragma unroll
    for (int i = 0; i < 8; i++) {
        int r = row0 + ((i < 4) ? (ty * 4 + i) : (64 + ty * 4 + (i - 4)));
#pragma unroll
        for (int j = 0; j < 8; j++) {
            int c = col0 + ((j < 4) ? (tx * 4 + j) : (64 + tx * 4 + (j - 4)));
            float v = acc[i][j];
            if (bias) v += bias[c];
            C[(size_t)r * N + c] = v;
        }
    }
}

// ---------------------------------------------------------------------------
// Flash attention, fp32. One block = 64 query rows of one (batch, head).
// BC=32 key/value tiles, online softmax. Q/K/V laid out (B*S, H*HD) row-major;
// head h lives in columns [h*HD, h*HD+64).
// ---------------------------------------------------------------------------
#define BR 64
#define BC 32
#define LDT 65   // smem row pitch for 64-wide tiles (conflict mitigation)
#define LDP 33   // smem row pitch for P tile

__global__ __launch_bounds__(256) void flash_kernel(
    const float* __restrict__ Q, const float* __restrict__ K,
    const float* __restrict__ V, float* __restrict__ O)
{
    __shared__ float Qs[BR][LDT];
    __shared__ float Ks[BC][LDT];
    __shared__ float Vs[BC][LDT];
    __shared__ float Ps[BR][LDP];

    const int tid = threadIdx.x;
    const int ty  = tid >> 4;   // 0..15 -> rows ty*4..+3
    const int tx  = tid & 15;   // 0..15

    const int bh = blockIdx.y;
    const int b  = bh / N_HEADS;
    const int h  = bh % N_HEADS;
    const int qrow0 = blockIdx.x * BR;
    const size_t base = (size_t)b * S_LEN * D_MODEL + (size_t)h * HD;

    // Load Q tile (64x64 floats, float4 loads, scalar stores into pitched smem)
    for (int idx = tid; idx < BR * (HD / 4); idx += 256) {
        int r  = idx >> 4;
        int c4 = (idx & 15) * 4;
        float4 v = *(const float4*)(Q + base + (size_t)(qrow0 + r) * D_MODEL + c4);
        Qs[r][c4 + 0] = v.x; Qs[r][c4 + 1] = v.y;
        Qs[r][c4 + 2] = v.z; Qs[r][c4 + 3] = v.w;
    }

    float o[4][4];
    float m_i[4], l_i[4];
#pragma unroll
    for (int i = 0; i < 4; i++) {
        m_i[i] = -1e30f; l_i[i] = 0.0f;
#pragma unroll
        for (int j = 0; j < 4; j++) o[i][j] = 0.0f;
    }
    __syncthreads();

    const float inv_sqrt_d = 0.03125f;  // 1/sqrt(1024): module scales by d_model!

    for (int kt = 0; kt < S_LEN / BC; kt++) {
        // Load K,V tiles (32x64 each): 512 float4 per tensor / 256 threads
        for (int idx = tid; idx < BC * (HD / 4); idx += 256) {
            int r  = idx >> 4;
            int c4 = (idx & 15) * 4;
            size_t g = base + (size_t)(kt * BC + r) * D_MODEL + c4;
            float4 kv = *(const float4*)(K + g);
            Ks[r][c4 + 0] = kv.x; Ks[r][c4 + 1] = kv.y;
            Ks[r][c4 + 2] = kv.z; Ks[r][c4 + 3] = kv.w;
            float4 vv = *(const float4*)(V + g);
            Vs[r][c4 + 0] = vv.x; Vs[r][c4 + 1] = vv.y;
            Vs[r][c4 + 2] = vv.z; Vs[r][c4 + 3] = vv.w;
        }
        __syncthreads();

        // S tile: rows ty*4+i (4), cols tx*2+j (2)
        float s[4][2];
#pragma unroll
        for (int i = 0; i < 4; i++) { s[i][0] = 0.0f; s[i][1] = 0.0f; }
#pragma unroll 8
        for (int d = 0; d < HD; d++) {
            float a[4], bb[2];
#pragma unroll
            for (int i = 0; i < 4; i++) a[i] = Qs[ty * 4 + i][d];
            bb[0] = Ks[tx * 2 + 0][d];
            bb[1] = Ks[tx * 2 + 1][d];
#pragma unroll
            for (int i = 0; i < 4; i++) {
                s[i][0] = fmaf(a[i], bb[0], s[i][0]);
                s[i][1] = fmaf(a[i], bb[1], s[i][1]);
            }
        }

        // Online softmax per row (replicated across the 16 tx lanes of a row)
#pragma unroll
        for (int i = 0; i < 4; i++) {
            s[i][0] *= inv_sqrt_d;
            s[i][1] *= inv_sqrt_d;
            float mt = fmaxf(s[i][0], s[i][1]);
#pragma unroll
            for (int off = 1; off < 16; off <<= 1)
                mt = fmaxf(mt, __shfl_xor_sync(0xffffffffu, mt, off));
            float m_new = fmaxf(m_i[i], mt);
            float scale = __expf(m_i[i] - m_new);
            float p0 = __expf(s[i][0] - m_new);
            float p1 = __expf(s[i][1] - m_new);
            float ps = p0 + p1;
#pragma unroll
            for (int off = 1; off < 16; off <<= 1)
                ps += __shfl_xor_sync(0xffffffffu, ps, off);
            l_i[i] = l_i[i] * scale + ps;
            m_i[i] = m_new;
#pragma unroll
            for (int jj = 0; jj < 4; jj++) o[i][jj] *= scale;
            Ps[ty * 4 + i][tx * 2 + 0] = p0;
            Ps[ty * 4 + i][tx * 2 + 1] = p1;
        }
        __syncthreads();

        // O += P * V : rows ty*4+i, hd cols tx*4+jj
#pragma unroll 4
        for (int j = 0; j < BC; j++) {
            float a[4], bb[4];
#pragma unroll
            for (int i = 0; i < 4; i++) a[i] = Ps[ty * 4 + i][j];
#pragma unroll
            for (int jj = 0; jj < 4; jj++) bb[jj] = Vs[j][tx * 4 + jj];
#pragma unroll
            for (int i = 0; i < 4; i++)
#pragma unroll
                for (int jj = 0; jj < 4; jj++)
                    o[i][jj] = fmaf(a[i], bb[jj], o[i][jj]);
        }
        __syncthreads();  // before next tile overwrites Ks/Vs/Ps
    }

    // Normalize and write out (float4-coalesced)
#pragma unroll
    for (int i = 0; i < 4; i++) {
        float inv_l = 1.0f / l_i[i];
        float4 v;
        v.x = o[i][0] * inv_l; v.y = o[i][1] * inv_l;
        v.z = o[i][2] * inv_l; v.w = o[i][3] * inv_l;
        *(float4*)(O + base + (size_t)(qrow0 + ty * 4 + i) * D_MODEL + tx * 4) = v;
    }
}

// ---------------------------------------------------------------------------
extern "C" void kernel_launch(void* const* d_in, const int* in_sizes, int n_in,
                              void* d_out, int out_size)
{
    const float* q  = (const float*)d_in[0];
    const float* k  = (const float*)d_in[1];
    const float* v  = (const float*)d_in[2];
    const float* Wq = (const float*)d_in[3];
    const float* Wk = (const float*)d_in[4];
    const float* Wv = (const float*)d_in[5];
    const float* Wo = (const float*)d_in[6];
    const float* bo = (const float*)d_in[7];
    float* out = (float*)d_out;

    float *Qb, *Kb, *Vb, *AOb;
    cudaGetSymbolAddress((void**)&Qb,  g_Q);
    cudaGetSymbolAddress((void**)&Kb,  g_K);
    cudaGetSymbolAddress((void**)&Vb,  g_V);
    cudaGetSymbolAddress((void**)&AOb, g_AO);

    dim3 ggrid(D_MODEL / 128, M_ROWS / 128);   // (8, 32)
    gemm_nt_kernel<<<ggrid, 256>>>(q, Wq, nullptr, Qb, M_ROWS, D_MODEL, D_MODEL);
    gemm_nt_kernel<<<ggrid, 256>>>(k, Wk, nullptr, Kb, M_ROWS, D_MODEL, D_MODEL);
    gemm_nt_kernel<<<ggrid, 256>>>(v, Wv, nullptr, Vb, M_ROWS, D_MODEL, D_MODEL);

    dim3 fgrid(S_LEN / BR, BATCH * N_HEADS);   // (32, 32)
    flash_kernel<<<fgrid, 256>>>(Qb, Kb, Vb, AOb);

    gemm_nt_kernel<<<ggrid, 256>>>(AOb, Wo, bo, out, M_ROWS, D_MODEL, D_MODEL);
}

// round 7
// speedup vs baseline: 1.3832x; 1.3832x over previous
#include <cuda_runtime.h>
#include <cuda_bf16.h>
#include <mma.h>
#include <cstdint>
#include <math.h>

using namespace nvcuda;

#define D_MODEL 1024
#define S_LEN   2048
#define BATCH   2
#define N_HEADS 16
#define HD      64
#define M_ROWS  (BATCH * S_LEN)   // 4096

// Scratch (no cudaMalloc allowed)
__device__ float g_Q[M_ROWS * D_MODEL];
__device__ float g_K[M_ROWS * D_MODEL];
__device__ float g_V[M_ROWS * D_MODEL];
__device__ float g_AO[M_ROWS * D_MODEL];

// ============================================================================
// WMMA split-bf16 NT GEMM: C[M,N] = A[M,K] * B[N,K]^T
// fp32 operands split into hi/lo bf16; C = Ah*Bh + Ah*Bl + Al*Bh (fp32 acc).
// CTA tile 128x128, BK=32, 8 warps in 2x4, warp tile 64x32 (4x2 wmma tiles).
// Double-buffered smem, single barrier per K-block, gmem overlapped w/compute.
// ============================================================================
#define GTM 128
#define GTN 128
#define BK  32
#define NKB (D_MODEL / BK)     // 32
#define PITCH 40               // bf16 elements per smem row (pad 32->40)
#define TSZ (128 * PITCH)      // 5120 bf16 per tile array
#define BUF_ELEMS (4 * TSZ)    // Ah, Al, Bh, Bl
#define GEMM_SMEM (2 * BUF_ELEMS * 2)   // bytes = 81920

__global__ __launch_bounds__(256) void gemm_wmma_kernel(
    const float* __restrict__ A, const float* __restrict__ B,
    float* __restrict__ C)
{
    extern __shared__ __nv_bfloat16 sm[];
    const int tid = threadIdx.x;
    const int wid = tid >> 5;
    const int warpM = wid >> 2;         // 0..1
    const int warpN = wid & 3;          // 0..3
    const int m0 = blockIdx.y * GTM;
    const int n0 = blockIdx.x * GTN;

    wmma::fragment<wmma::accumulator, 16, 16, 16, float> acc[4][2];
#pragma unroll
    for (int i = 0; i < 4; i++)
#pragma unroll
        for (int j = 0; j < 2; j++) wmma::fill_fragment(acc[i][j], 0.0f);

    float4 aReg[4], bReg[4];

    // --- load kb-th K-block of A and B tiles into registers ---
    auto ldregs = [&](int kb) {
#pragma unroll
        for (int i = 0; i < 4; i++) {
            int idx = tid + i * 256;
            int r = idx >> 3;            // 0..127
            int c4 = (idx & 7) * 4;      // 0..28
            aReg[i] = *(const float4*)(A + (size_t)(m0 + r) * D_MODEL + kb * BK + c4);
            bReg[i] = *(const float4*)(B + (size_t)(n0 + r) * D_MODEL + kb * BK + c4);
        }
    };
    // --- split-convert registers and store into smem buffer ---
    auto stregs = [&](int buf) {
        __nv_bfloat16* Ah = sm + buf * BUF_ELEMS;
        __nv_bfloat16* Al = Ah + TSZ;
        __nv_bfloat16* Bh = Ah + 2 * TSZ;
        __nv_bfloat16* Bl = Ah + 3 * TSZ;
#pragma unroll
        for (int i = 0; i < 4; i++) {
            int idx = tid + i * 256;
            int r = idx >> 3;
            int c4 = (idx & 7) * 4;
            float va[4] = {aReg[i].x, aReg[i].y, aReg[i].z, aReg[i].w};
            float vb[4] = {bReg[i].x, bReg[i].y, bReg[i].z, bReg[i].w};
#pragma unroll
            for (int e = 0; e < 4; e++) {
                __nv_bfloat16 ah = __float2bfloat16(va[e]);
                __nv_bfloat16 bh = __float2bfloat16(vb[e]);
                Ah[r * PITCH + c4 + e] = ah;
                Al[r * PITCH + c4 + e] = __float2bfloat16(va[e] - __bfloat162float(ah));
                Bh[r * PITCH + c4 + e] = bh;
                Bl[r * PITCH + c4 + e] = __float2bfloat16(vb[e] - __bfloat162float(bh));
            }
        }
    };
    // --- compute current buffer: 2 ksteps of 16, 3 split passes ---
    auto compute = [&](int buf) {
        const __nv_bfloat16* Ah = sm + buf * BUF_ELEMS;
        const __nv_bfloat16* Al = Ah + TSZ;
        const __nv_bfloat16* Bh = Ah + 2 * TSZ;
        const __nv_bfloat16* Bl = Ah + 3 * TSZ;
#pragma unroll
        for (int ks = 0; ks < BK / 16; ks++) {
            wmma::fragment<wmma::matrix_a, 16, 16, 16, __nv_bfloat16, wmma::row_major> fa[4];
            wmma::fragment<wmma::matrix_b, 16, 16, 16, __nv_bfloat16, wmma::col_major> fb[2];
            // pass 1: Ah * Bh
#pragma unroll
            for (int i = 0; i < 4; i++)
                wmma::load_matrix_sync(fa[i], Ah + (warpM * 64 + i * 16) * PITCH + ks * 16, PITCH);
#pragma unroll
            for (int j = 0; j < 2; j++)
                wmma::load_matrix_sync(fb[j], Bh + (warpN * 32 + j * 16) * PITCH + ks * 16, PITCH);
#pragma unroll
            for (int i = 0; i < 4; i++)
#pragma unroll
                for (int j = 0; j < 2; j++)
                    wmma::mma_sync(acc[i][j], fa[i], fb[j], acc[i][j]);
            // pass 2: Ah * Bl
#pragma unroll
            for (int j = 0; j < 2; j++)
                wmma::load_matrix_sync(fb[j], Bl + (warpN * 32 + j * 16) * PITCH + ks * 16, PITCH);
#pragma unroll
            for (int i = 0; i < 4; i++)
#pragma unroll
                for (int j = 0; j < 2; j++)
                    wmma::mma_sync(acc[i][j], fa[i], fb[j], acc[i][j]);
            // pass 3: Al * Bh
#pragma unroll
            for (int i = 0; i < 4; i++)
                wmma::load_matrix_sync(fa[i], Al + (warpM * 64 + i * 16) * PITCH + ks * 16, PITCH);
#pragma unroll
            for (int j = 0; j < 2; j++)
                wmma::load_matrix_sync(fb[j], Bh + (warpN * 32 + j * 16) * PITCH + ks * 16, PITCH);
#pragma unroll
            for (int i = 0; i < 4; i++)
#pragma unroll
                for (int j = 0; j < 2; j++)
                    wmma::mma_sync(acc[i][j], fa[i], fb[j], acc[i][j]);
        }
    };

    ldregs(0);
    stregs(0);
    __syncthreads();

    for (int kb = 0; kb < NKB; kb++) {
        const int cur = kb & 1;
        if (kb + 1 < NKB) ldregs(kb + 1);   // gmem loads overlap compute below
        compute(cur);
        if (kb + 1 < NKB) stregs(cur ^ 1);  // other buffer: no alias with cur
        __syncthreads();
    }

    // Epilogue: direct wmma store to gmem (row-major, ld=D_MODEL)
#pragma unroll
    for (int i = 0; i < 4; i++)
#pragma unroll
        for (int j = 0; j < 2; j++)
            wmma::store_matrix_sync(
                C + (size_t)(m0 + warpM * 64 + i * 16) * D_MODEL + n0 + warpN * 32 + j * 16,
                acc[i][j], D_MODEL, wmma::mem_row_major);
}

// Bias add for the final projection: out[r][c] += bo[c]
__global__ __launch_bounds__(256) void bias_kernel(float* __restrict__ out,
                                                   const float* __restrict__ bo)
{
    int idx = blockIdx.x * 256 + threadIdx.x;           // float4 index
    int c4 = (idx & (D_MODEL / 4 - 1)) * 4;
    float4 v = *(float4*)(out + (size_t)idx * 4);
    v.x += bo[c4]; v.y += bo[c4 + 1]; v.z += bo[c4 + 2]; v.w += bo[c4 + 3];
    *(float4*)(out + (size_t)idx * 4) = v;
}

// ============================================================================
// Flash attention fp32 (unchanged from R4): BR=64, BC=64, 4x4 thread tile.
// ============================================================================
#define BR 64
#define BC 64
#define FP 76
#define FL_SMEM (4 * 64 * FP * 4)   // 77824 B

__global__ __launch_bounds__(256) void flash_kernel(
    const float* __restrict__ Q, const float* __restrict__ K,
    const float* __restrict__ V, float* __restrict__ O)
{
    extern __shared__ float fsm[];
    float* Qs = fsm;
    float* Ks = Qs + 64 * FP;
    float* Vs = Ks + 64 * FP;
    float* Ps = Vs + 64 * FP;

    const int tid = threadIdx.x;
    const int ty  = tid >> 4;
    const int tx  = tid & 15;

    const int bh = blockIdx.y;
    const int b  = bh / N_HEADS;
    const int h  = bh % N_HEADS;
    const int qrow0 = blockIdx.x * BR;
    const size_t base = (size_t)b * S_LEN * D_MODEL + (size_t)h * HD;

#pragma unroll
    for (int it = 0; it < 4; it++) {
        int idx = tid + it * 256;
        int r = idx >> 4;
        int c4 = (idx & 15) * 4;
        *(float4*)&Qs[r * FP + c4] =
            *(const float4*)(Q + base + (size_t)(qrow0 + r) * D_MODEL + c4);
    }

    float o[4][4];
    float m_i[4], l_i[4];
#pragma unroll
    for (int i = 0; i < 4; i++) {
        m_i[i] = -1e30f; l_i[i] = 0.0f;
#pragma unroll
        for (int j = 0; j < 4; j++) o[i][j] = 0.0f;
    }
    __syncthreads();

    const float inv_sqrt_d = 0.03125f;  // 1/sqrt(1024): module scales by d_model

    for (int kt = 0; kt < S_LEN / BC; kt++) {
#pragma unroll
        for (int it = 0; it < 4; it++) {
            int idx = tid + it * 256;
            int r = idx >> 4;
            int c4 = (idx & 15) * 4;
            size_t g = base + (size_t)(kt * BC + r) * D_MODEL + c4;
            *(float4*)&Ks[r * FP + c4] = *(const float4*)(K + g);
            *(float4*)&Vs[r * FP + c4] = *(const float4*)(V + g);
        }
        __syncthreads();

        float s[4][4];
#pragma unroll
        for (int i = 0; i < 4; i++)
#pragma unroll
            for (int j = 0; j < 4; j++) s[i][j] = 0.0f;

#pragma unroll
        for (int d = 0; d < HD; d += 4) {
            float4 qa[4], kb4[4];
#pragma unroll
            for (int i = 0; i < 4; i++) qa[i] = *(float4*)&Qs[(ty * 4 + i) * FP + d];
#pragma unroll
            for (int j = 0; j < 4; j++) kb4[j] = *(float4*)&Ks[(j * 16 + tx) * FP + d];
#pragma unroll
            for (int i = 0; i < 4; i++)
#pragma unroll
                for (int j = 0; j < 4; j++)
                    s[i][j] += qa[i].x * kb4[j].x + qa[i].y * kb4[j].y +
                               qa[i].z * kb4[j].z + qa[i].w * kb4[j].w;
        }

#pragma unroll
        for (int i = 0; i < 4; i++) {
#pragma unroll
            for (int j = 0; j < 4; j++) s[i][j] *= inv_sqrt_d;
            float mt = fmaxf(fmaxf(s[i][0], s[i][1]), fmaxf(s[i][2], s[i][3]));
#pragma unroll
            for (int off = 1; off < 16; off <<= 1)
                mt = fmaxf(mt, __shfl_xor_sync(0xffffffffu, mt, off));
            float m_new = fmaxf(m_i[i], mt);
            float scale = __expf(m_i[i] - m_new);
            float p[4], ps = 0.0f;
#pragma unroll
            for (int j = 0; j < 4; j++) { p[j] = __expf(s[i][j] - m_new); ps += p[j]; }
#pragma unroll
            for (int off = 1; off < 16; off <<= 1)
                ps += __shfl_xor_sync(0xffffffffu, ps, off);
            l_i[i] = l_i[i] * scale + ps;
            m_i[i] = m_new;
#pragma unroll
            for (int jj = 0; jj < 4; jj++) o[i][jj] *= scale;
#pragma unroll
            for (int j = 0; j < 4; j++)
                Ps[(ty * 4 + i) * FP + j * 16 + tx] = p[j];
        }
        __syncthreads();

#pragma unroll
        for (int j0 = 0; j0 < BC; j0 += 4) {
            float4 pa[4], vb[4];
#pragma unroll
            for (int i = 0; i < 4; i++) pa[i] = *(float4*)&Ps[(ty * 4 + i) * FP + j0];
#pragma unroll
            for (int dj = 0; dj < 4; dj++) vb[dj] = *(float4*)&Vs[(j0 + dj) * FP + tx * 4];
#pragma unroll
            for (int i = 0; i < 4; i++) {
                o[i][0] += pa[i].x * vb[0].x + pa[i].y * vb[1].x + pa[i].z * vb[2].x + pa[i].w * vb[3].x;
                o[i][1] += pa[i].x * vb[0].y + pa[i].y * vb[1].y + pa[i].z * vb[2].y + pa[i].w * vb[3].y;
                o[i][2] += pa[i].x * vb[0].z + pa[i].y * vb[1].z + pa[i].z * vb[2].z + pa[i].w * vb[3].z;
                o[i][3] += pa[i].x * vb[0].w + pa[i].y * vb[1].w + pa[i].z * vb[2].w + pa[i].w * vb[3].w;
            }
        }
        __syncthreads();
    }

#pragma unroll
    for (int i = 0; i < 4; i++) {
        float inv_l = 1.0f / l_i[i];
        float4 v;
        v.x = o[i][0] * inv_l; v.y = o[i][1] * inv_l;
        v.z = o[i][2] * inv_l; v.w = o[i][3] * inv_l;
        *(float4*)(O + base + (size_t)(qrow0 + ty * 4 + i) * D_MODEL + tx * 4) = v;
    }
}

// ---------------------------------------------------------------------------
extern "C" void kernel_launch(void* const* d_in, const int* in_sizes, int n_in,
                              void* d_out, int out_size)
{
    const float* q  = (const float*)d_in[0];
    const float* k  = (const float*)d_in[1];
    const float* v  = (const float*)d_in[2];
    const float* Wq = (const float*)d_in[3];
    const float* Wk = (const float*)d_in[4];
    const float* Wv = (const float*)d_in[5];
    const float* Wo = (const float*)d_in[6];
    const float* bo = (const float*)d_in[7];
    float* out = (float*)d_out;

    float *Qb, *Kb, *Vb, *AOb;
    cudaGetSymbolAddress((void**)&Qb,  g_Q);
    cudaGetSymbolAddress((void**)&Kb,  g_K);
    cudaGetSymbolAddress((void**)&Vb,  g_V);
    cudaGetSymbolAddress((void**)&AOb, g_AO);

    cudaFuncSetAttribute(gemm_wmma_kernel, cudaFuncAttributeMaxDynamicSharedMemorySize, GEMM_SMEM);
    cudaFuncSetAttribute(flash_kernel,     cudaFuncAttributeMaxDynamicSharedMemorySize, FL_SMEM);

    dim3 ggrid(D_MODEL / GTN, M_ROWS / GTM);   // (8, 32) = 256 CTAs
    gemm_wmma_kernel<<<ggrid, 256, GEMM_SMEM>>>(q, Wq, Qb);
    gemm_wmma_kernel<<<ggrid, 256, GEMM_SMEM>>>(k, Wk, Kb);
    gemm_wmma_kernel<<<ggrid, 256, GEMM_SMEM>>>(v, Wv, Vb);

    dim3 fgrid(S_LEN / BR, BATCH * N_HEADS);   // (32, 32)
    flash_kernel<<<fgrid, 256, FL_SMEM>>>(Qb, Kb, Vb, AOb);

    gemm_wmma_kernel<<<ggrid, 256, GEMM_SMEM>>>(AOb, Wo, out);
    bias_kernel<<<M_ROWS * D_MODEL / 4 / 256, 256>>>(out, bo);
}

// round 8
// speedup vs baseline: 1.9309x; 1.3960x over previous
#include <cuda_runtime.h>
#include <cuda_bf16.h>
#include <mma.h>
#include <cstdint>
#include <math.h>

using namespace nvcuda;

#define D_MODEL 1024
#define S_LEN   2048
#define BATCH   2
#define N_HEADS 16
#define HD      64
#define M_ROWS  (BATCH * S_LEN)   // 4096

// Scratch (no cudaMalloc allowed)
__device__ float g_Q[M_ROWS * D_MODEL];
__device__ float g_K[M_ROWS * D_MODEL];
__device__ float g_V[M_ROWS * D_MODEL];
__device__ float g_AO[M_ROWS * D_MODEL];

// ============================================================================
// WMMA split-bf16 NT GEMM (unchanged from R7 — measured ~133us/GEMM)
// ============================================================================
#define GTM 128
#define GTN 128
#define BK  32
#define NKB (D_MODEL / BK)     // 32
#define PITCH 40
#define TSZ (128 * PITCH)
#define BUF_ELEMS (4 * TSZ)
#define GEMM_SMEM (2 * BUF_ELEMS * 2)   // 81920 B

__global__ __launch_bounds__(256) void gemm_wmma_kernel(
    const float* __restrict__ A, const float* __restrict__ B,
    float* __restrict__ C)
{
    extern __shared__ __nv_bfloat16 sm[];
    const int tid = threadIdx.x;
    const int wid = tid >> 5;
    const int warpM = wid >> 2;
    const int warpN = wid & 3;
    const int m0 = blockIdx.y * GTM;
    const int n0 = blockIdx.x * GTN;

    wmma::fragment<wmma::accumulator, 16, 16, 16, float> acc[4][2];
#pragma unroll
    for (int i = 0; i < 4; i++)
#pragma unroll
        for (int j = 0; j < 2; j++) wmma::fill_fragment(acc[i][j], 0.0f);

    float4 aReg[4], bReg[4];

    auto ldregs = [&](int kb) {
#pragma unroll
        for (int i = 0; i < 4; i++) {
            int idx = tid + i * 256;
            int r = idx >> 3;
            int c4 = (idx & 7) * 4;
            aReg[i] = *(const float4*)(A + (size_t)(m0 + r) * D_MODEL + kb * BK + c4);
            bReg[i] = *(const float4*)(B + (size_t)(n0 + r) * D_MODEL + kb * BK + c4);
        }
    };
    auto stregs = [&](int buf) {
        __nv_bfloat16* Ah = sm + buf * BUF_ELEMS;
        __nv_bfloat16* Al = Ah + TSZ;
        __nv_bfloat16* Bh = Ah + 2 * TSZ;
        __nv_bfloat16* Bl = Ah + 3 * TSZ;
#pragma unroll
        for (int i = 0; i < 4; i++) {
            int idx = tid + i * 256;
            int r = idx >> 3;
            int c4 = (idx & 7) * 4;
            float va[4] = {aReg[i].x, aReg[i].y, aReg[i].z, aReg[i].w};
            float vb[4] = {bReg[i].x, bReg[i].y, bReg[i].z, bReg[i].w};
#pragma unroll
            for (int e = 0; e < 4; e++) {
                __nv_bfloat16 ah = __float2bfloat16(va[e]);
                __nv_bfloat16 bh = __float2bfloat16(vb[e]);
                Ah[r * PITCH + c4 + e] = ah;
                Al[r * PITCH + c4 + e] = __float2bfloat16(va[e] - __bfloat162float(ah));
                Bh[r * PITCH + c4 + e] = bh;
                Bl[r * PITCH + c4 + e] = __float2bfloat16(vb[e] - __bfloat162float(bh));
            }
        }
    };
    auto compute = [&](int buf) {
        const __nv_bfloat16* Ah = sm + buf * BUF_ELEMS;
        const __nv_bfloat16* Al = Ah + TSZ;
        const __nv_bfloat16* Bh = Ah + 2 * TSZ;
        const __nv_bfloat16* Bl = Ah + 3 * TSZ;
#pragma unroll
        for (int ks = 0; ks < BK / 16; ks++) {
            wmma::fragment<wmma::matrix_a, 16, 16, 16, __nv_bfloat16, wmma::row_major> fa[4];
            wmma::fragment<wmma::matrix_b, 16, 16, 16, __nv_bfloat16, wmma::col_major> fb[2];
#pragma unroll
            for (int i = 0; i < 4; i++)
                wmma::load_matrix_sync(fa[i], Ah + (warpM * 64 + i * 16) * PITCH + ks * 16, PITCH);
#pragma unroll
            for (int j = 0; j < 2; j++)
                wmma::load_matrix_sync(fb[j], Bh + (warpN * 32 + j * 16) * PITCH + ks * 16, PITCH);
#pragma unroll
            for (int i = 0; i < 4; i++)
#pragma unroll
                for (int j = 0; j < 2; j++)
                    wmma::mma_sync(acc[i][j], fa[i], fb[j], acc[i][j]);
#pragma unroll
            for (int j = 0; j < 2; j++)
                wmma::load_matrix_sync(fb[j], Bl + (warpN * 32 + j * 16) * PITCH + ks * 16, PITCH);
#pragma unroll
            for (int i = 0; i < 4; i++)
#pragma unroll
                for (int j = 0; j < 2; j++)
                    wmma::mma_sync(acc[i][j], fa[i], fb[j], acc[i][j]);
#pragma unroll
            for (int i = 0; i < 4; i++)
                wmma::load_matrix_sync(fa[i], Al + (warpM * 64 + i * 16) * PITCH + ks * 16, PITCH);
#pragma unroll
            for (int j = 0; j < 2; j++)
                wmma::load_matrix_sync(fb[j], Bh + (warpN * 32 + j * 16) * PITCH + ks * 16, PITCH);
#pragma unroll
            for (int i = 0; i < 4; i++)
#pragma unroll
                for (int j = 0; j < 2; j++)
                    wmma::mma_sync(acc[i][j], fa[i], fb[j], acc[i][j]);
        }
    };

    ldregs(0);
    stregs(0);
    __syncthreads();

    for (int kb = 0; kb < NKB; kb++) {
        const int cur = kb & 1;
        if (kb + 1 < NKB) ldregs(kb + 1);
        compute(cur);
        if (kb + 1 < NKB) stregs(cur ^ 1);
        __syncthreads();
    }

#pragma unroll
    for (int i = 0; i < 4; i++)
#pragma unroll
        for (int j = 0; j < 2; j++)
            wmma::store_matrix_sync(
                C + (size_t)(m0 + warpM * 64 + i * 16) * D_MODEL + n0 + warpN * 32 + j * 16,
                acc[i][j], D_MODEL, wmma::mem_row_major);
}

__global__ __launch_bounds__(256) void bias_kernel(float* __restrict__ out,
                                                   const float* __restrict__ bo)
{
    int idx = blockIdx.x * 256 + threadIdx.x;
    int c4 = (idx & (D_MODEL / 4 - 1)) * 4;
    float4 v = *(float4*)(out + (size_t)idx * 4);
    v.x += bo[c4]; v.y += bo[c4 + 1]; v.z += bo[c4 + 2]; v.w += bo[c4 + 3];
    *(float4*)(out + (size_t)idx * 4) = v;
}

// ============================================================================
// Tensor-core flash attention (FA2 style, mma.sync.m16n8k16 bf16, split hi/lo)
// CTA = 128 query rows of one (b,h), 8 warps x 16 rows. BC = 64 keys/iter.
// Q held in registers as A-frags. K [key][hd], V transposed [hd][key] in smem.
// ============================================================================
#define FBR 128
#define FBC 64
#define KP  72              // smem pitch (bf16 elems) for K and Vt tiles
#define FL_SMEM 36864       // 4 tiles * 64*72*2 B (Q fp32 staging fits inside)

__device__ __forceinline__ uint32_t pack_bf2(float a, float b) {
    __nv_bfloat162 t;
    t.x = __float2bfloat16(a);
    t.y = __float2bfloat16(b);
    return *(uint32_t*)&t;
}

__device__ __forceinline__ void mma_bf16(float* c, const uint32_t* a,
                                         uint32_t b0, uint32_t b1) {
    asm volatile(
        "mma.sync.aligned.m16n8k16.row.col.f32.bf16.bf16.f32 "
        "{%0,%1,%2,%3}, {%4,%5,%6,%7}, {%8,%9}, {%0,%1,%2,%3};"
        : "+f"(c[0]), "+f"(c[1]), "+f"(c[2]), "+f"(c[3])
        : "r"(a[0]), "r"(a[1]), "r"(a[2]), "r"(a[3]), "r"(b0), "r"(b1));
}

__global__ __launch_bounds__(256) void flash_tc_kernel(
    const float* __restrict__ Q, const float* __restrict__ K,
    const float* __restrict__ V, float* __restrict__ O)
{
    extern __shared__ char fsm[];
    __nv_bfloat16* Kh = (__nv_bfloat16*)fsm;             // [64][KP]
    __nv_bfloat16* Kl = Kh + 64 * KP;
    __nv_bfloat16* Vh = Kh + 2 * 64 * KP;                // transposed [hd][key]
    __nv_bfloat16* Vl = Kh + 3 * 64 * KP;
    float* Qst = (float*)fsm;                            // staging, pitch 68

    const int tid  = threadIdx.x;
    const int wid  = tid >> 5;
    const int lane = tid & 31;
    const int g    = lane >> 2;      // 0..7
    const int t    = lane & 3;       // 0..3

    const int bh = blockIdx.y;
    const int b  = bh / N_HEADS;
    const int h  = bh % N_HEADS;
    const int qrow0 = blockIdx.x * FBR;
    const size_t base = (size_t)b * S_LEN * D_MODEL + (size_t)h * HD;

    // ---- stage Q tile (128x64 fp32), then build per-warp A-fragments ----
#pragma unroll
    for (int it = 0; it < 8; it++) {
        int idx = tid + it * 256;
        int r = idx >> 4;
        int c4 = (idx & 15) * 4;
        *(float4*)&Qst[r * 68 + c4] =
            *(const float4*)(Q + base + (size_t)(qrow0 + r) * D_MODEL + c4);
    }
    __syncthreads();

    uint32_t qh[4][4], ql[4][4];
    {
        const int ra = wid * 16 + g;
#pragma unroll
        for (int ks = 0; ks < 4; ks++) {
#pragma unroll
            for (int half = 0; half < 2; half++) {
#pragma unroll
                for (int cp = 0; cp < 2; cp++) {
                    int r = ra + half * 8;
                    int c = ks * 16 + t * 2 + cp * 8;
                    float f0 = Qst[r * 68 + c];
                    float f1 = Qst[r * 68 + c + 1];
                    __nv_bfloat16 h0 = __float2bfloat16(f0);
                    __nv_bfloat16 h1 = __float2bfloat16(f1);
                    int ri = half + cp * 2;   // reg order: (a0a1),(a2a3),(a4a5),(a6a7)
                    __nv_bfloat162 hp; hp.x = h0; hp.y = h1;
                    qh[ks][ri] = *(uint32_t*)&hp;
                    ql[ks][ri] = pack_bf2(f0 - __bfloat162float(h0),
                                          f1 - __bfloat162float(h1));
                }
            }
        }
    }
    __syncthreads();   // staging area about to be overwritten by K/V

    float m0r = -1e30f, m1r = -1e30f, l0r = 0.0f, l1r = 0.0f;
    float co[8][4];
#pragma unroll
    for (int j = 0; j < 8; j++)
#pragma unroll
        for (int e = 0; e < 4; e++) co[j][e] = 0.0f;

    const float inv_sqrt_d = 0.03125f;   // 1/sqrt(1024): module scales by d_model

    for (int kt = 0; kt < S_LEN / FBC; kt++) {
        const int key0 = kt * FBC;
        // ---- load + split K (into [key][hd]) and V (transposed [hd][key]) ----
#pragma unroll
        for (int it = 0; it < 4; it++) {
            int idx = tid + it * 256;
            int kr = idx >> 4;
            int c4 = (idx & 15) * 4;
            size_t gaddr = base + (size_t)(key0 + kr) * D_MODEL + c4;
            float4 kv = *(const float4*)(K + gaddr);
            float4 vv = *(const float4*)(V + gaddr);
            float ka[4] = {kv.x, kv.y, kv.z, kv.w};
            float va[4] = {vv.x, vv.y, vv.z, vv.w};
            // K: packed 2-elem stores, row kr
            __nv_bfloat16 k0 = __float2bfloat16(ka[0]);
            __nv_bfloat16 k1 = __float2bfloat16(ka[1]);
            __nv_bfloat16 k2 = __float2bfloat16(ka[2]);
            __nv_bfloat16 k3 = __float2bfloat16(ka[3]);
            __nv_bfloat162 p01; p01.x = k0; p01.y = k1;
            __nv_bfloat162 p23; p23.x = k2; p23.y = k3;
            *(uint32_t*)&Kh[kr * KP + c4]     = *(uint32_t*)&p01;
            *(uint32_t*)&Kh[kr * KP + c4 + 2] = *(uint32_t*)&p23;
            *(uint32_t*)&Kl[kr * KP + c4]     = pack_bf2(ka[0] - __bfloat162float(k0),
                                                         ka[1] - __bfloat162float(k1));
            *(uint32_t*)&Kl[kr * KP + c4 + 2] = pack_bf2(ka[2] - __bfloat162float(k2),
                                                         ka[3] - __bfloat162float(k3));
            // V: transposed scalar stores
#pragma unroll
            for (int e = 0; e < 4; e++) {
                __nv_bfloat16 vh = __float2bfloat16(va[e]);
                Vh[(c4 + e) * KP + kr] = vh;
                Vl[(c4 + e) * KP + kr] = __float2bfloat16(va[e] - __bfloat162float(vh));
            }
        }
        __syncthreads();

        // ---- S = Q K^T (split, 3 passes fused per fragment pair) ----
        float cs[8][4];
#pragma unroll
        for (int j = 0; j < 8; j++)
#pragma unroll
            for (int e = 0; e < 4; e++) cs[j][e] = 0.0f;

#pragma unroll
        for (int jn = 0; jn < 8; jn++) {
            const int krow = (jn * 8 + g) * KP;
#pragma unroll
            for (int ks = 0; ks < 4; ks++) {
                const int cofs = ks * 16 + t * 2;
                uint32_t bh0 = *(const uint32_t*)&Kh[krow + cofs];
                uint32_t bh1 = *(const uint32_t*)&Kh[krow + cofs + 8];
                uint32_t bl0 = *(const uint32_t*)&Kl[krow + cofs];
                uint32_t bl1 = *(const uint32_t*)&Kl[krow + cofs + 8];
                mma_bf16(cs[jn], qh[ks], bh0, bh1);
                mma_bf16(cs[jn], qh[ks], bl0, bl1);
                mma_bf16(cs[jn], ql[ks], bh0, bh1);
            }
        }

        // ---- online softmax (rows g and g+8 of this warp's 16) ----
        float mt0 = -1e30f, mt1 = -1e30f;
#pragma unroll
        for (int j = 0; j < 8; j++) {
#pragma unroll
            for (int e = 0; e < 4; e++) cs[j][e] *= inv_sqrt_d;
            mt0 = fmaxf(mt0, fmaxf(cs[j][0], cs[j][1]));
            mt1 = fmaxf(mt1, fmaxf(cs[j][2], cs[j][3]));
        }
        mt0 = fmaxf(mt0, __shfl_xor_sync(0xffffffffu, mt0, 1));
        mt0 = fmaxf(mt0, __shfl_xor_sync(0xffffffffu, mt0, 2));
        mt1 = fmaxf(mt1, __shfl_xor_sync(0xffffffffu, mt1, 1));
        mt1 = fmaxf(mt1, __shfl_xor_sync(0xffffffffu, mt1, 2));

        float mn0 = fmaxf(m0r, mt0);
        float mn1 = fmaxf(m1r, mt1);
        float sc0 = __expf(m0r - mn0);
        float sc1 = __expf(m1r - mn1);

        float ps0 = 0.0f, ps1 = 0.0f;
#pragma unroll
        for (int j = 0; j < 8; j++) {
            cs[j][0] = __expf(cs[j][0] - mn0);
            cs[j][1] = __expf(cs[j][1] - mn0);
            cs[j][2] = __expf(cs[j][2] - mn1);
            cs[j][3] = __expf(cs[j][3] - mn1);
            ps0 += cs[j][0] + cs[j][1];
            ps1 += cs[j][2] + cs[j][3];
        }
        ps0 += __shfl_xor_sync(0xffffffffu, ps0, 1);
        ps0 += __shfl_xor_sync(0xffffffffu, ps0, 2);
        ps1 += __shfl_xor_sync(0xffffffffu, ps1, 1);
        ps1 += __shfl_xor_sync(0xffffffffu, ps1, 2);

        l0r = l0r * sc0 + ps0;
        l1r = l1r * sc1 + ps1;
        m0r = mn0;
        m1r = mn1;

#pragma unroll
        for (int j = 0; j < 8; j++) {
            co[j][0] *= sc0; co[j][1] *= sc0;
            co[j][2] *= sc1; co[j][3] *= sc1;
        }

        // ---- O += P V (P from accum regs -> A frags, no smem/shfl) ----
#pragma unroll
        for (int ks = 0; ks < 4; ks++) {
            uint32_t ph[4], pl[4];
            // A-frag reg order: (a0a1)=row g cols 2t,2t+1 = tile 2ks c0,c1
            ph[0] = pack_bf2(cs[2 * ks][0], cs[2 * ks][1]);
            ph[1] = pack_bf2(cs[2 * ks][2], cs[2 * ks][3]);
            ph[2] = pack_bf2(cs[2 * ks + 1][0], cs[2 * ks + 1][1]);
            ph[3] = pack_bf2(cs[2 * ks + 1][2], cs[2 * ks + 1][3]);
            {
                __nv_bfloat162 t0 = *(__nv_bfloat162*)&ph[0];
                pl[0] = pack_bf2(cs[2 * ks][0] - __bfloat162float(t0.x),
                                 cs[2 * ks][1] - __bfloat162float(t0.y));
                __nv_bfloat162 t1 = *(__nv_bfloat162*)&ph[1];
                pl[1] = pack_bf2(cs[2 * ks][2] - __bfloat162float(t1.x),
                                 cs[2 * ks][3] - __bfloat162float(t1.y));
                __nv_bfloat162 t2 = *(__nv_bfloat162*)&ph[2];
                pl[2] = pack_bf2(cs[2 * ks + 1][0] - __bfloat162float(t2.x),
                                 cs[2 * ks + 1][1] - __bfloat162float(t2.y));
                __nv_bfloat162 t3 = *(__nv_bfloat162*)&ph[3];
                pl[3] = pack_bf2(cs[2 * ks + 1][2] - __bfloat162float(t3.x),
                                 cs[2 * ks + 1][3] - __bfloat162float(t3.y));
            }
#pragma unroll
            for (int jn = 0; jn < 8; jn++) {
                const int vrow = (jn * 8 + g) * KP;
                const int cofs = ks * 16 + t * 2;
                uint32_t vh0 = *(const uint32_t*)&Vh[vrow + cofs];
                uint32_t vh1 = *(const uint32_t*)&Vh[vrow + cofs + 8];
                uint32_t vl0 = *(const uint32_t*)&Vl[vrow + cofs];
                uint32_t vl1 = *(const uint32_t*)&Vl[vrow + cofs + 8];
                mma_bf16(co[jn], ph, vh0, vh1);
                mma_bf16(co[jn], ph, vl0, vl1);
                mma_bf16(co[jn], pl, vh0, vh1);
            }
        }
        __syncthreads();   // before next iteration overwrites K/V tiles
    }

    // ---- normalize + write out ----
    const float inv_l0 = 1.0f / l0r;
    const float inv_l1 = 1.0f / l1r;
    const int r0 = qrow0 + wid * 16 + g;
#pragma unroll
    for (int j = 0; j < 8; j++) {
        int c = j * 8 + t * 2;
        float2 v0 = {co[j][0] * inv_l0, co[j][1] * inv_l0};
        float2 v1 = {co[j][2] * inv_l1, co[j][3] * inv_l1};
        *(float2*)(O + base + (size_t)r0 * D_MODEL + c) = v0;
        *(float2*)(O + base + (size_t)(r0 + 8) * D_MODEL + c) = v1;
    }
}

// ---------------------------------------------------------------------------
extern "C" void kernel_launch(void* const* d_in, const int* in_sizes, int n_in,
                              void* d_out, int out_size)
{
    const float* q  = (const float*)d_in[0];
    const float* k  = (const float*)d_in[1];
    const float* v  = (const float*)d_in[2];
    const float* Wq = (const float*)d_in[3];
    const float* Wk = (const float*)d_in[4];
    const float* Wv = (const float*)d_in[5];
    const float* Wo = (const float*)d_in[6];
    const float* bo = (const float*)d_in[7];
    float* out = (float*)d_out;

    float *Qb, *Kb, *Vb, *AOb;
    cudaGetSymbolAddress((void**)&Qb,  g_Q);
    cudaGetSymbolAddress((void**)&Kb,  g_K);
    cudaGetSymbolAddress((void**)&Vb,  g_V);
    cudaGetSymbolAddress((void**)&AOb, g_AO);

    cudaFuncSetAttribute(gemm_wmma_kernel, cudaFuncAttributeMaxDynamicSharedMemorySize, GEMM_SMEM);
    cudaFuncSetAttribute(flash_tc_kernel,  cudaFuncAttributeMaxDynamicSharedMemorySize, FL_SMEM);

    dim3 ggrid(D_MODEL / GTN, M_ROWS / GTM);   // (8, 32)
    gemm_wmma_kernel<<<ggrid, 256, GEMM_SMEM>>>(q, Wq, Qb);
    gemm_wmma_kernel<<<ggrid, 256, GEMM_SMEM>>>(k, Wk, Kb);
    gemm_wmma_kernel<<<ggrid, 256, GEMM_SMEM>>>(v, Wv, Vb);

    dim3 fgrid(S_LEN / FBR, BATCH * N_HEADS);  // (16, 32) = 512 CTAs
    flash_tc_kernel<<<fgrid, 256, FL_SMEM>>>(Qb, Kb, Vb, AOb);

    gemm_wmma_kernel<<<ggrid, 256, GEMM_SMEM>>>(AOb, Wo, out);
    bias_kernel<<<M_ROWS * D_MODEL / 4 / 256, 256>>>(out, bo);
}